// round 5
// baseline (speedup 1.0000x reference)
#include <cuda_runtime.h>
#include <cstdint>

#define NN   50000
#define DIN  96
#define DOUT 128
#define NE   800000
#define NB   49              // ceil(NN/1024)
#define NT   1563            // ceil(NN/32) row-tiles

// ---------------- device scratch (no allocs allowed) ----------------
__device__ __align__(16) float g_agg[NN * DIN];
__device__ int g_cnt[NN];        // zeroed at end of agg for next replay
__device__ int g_rowstart[NN];
__device__ int g_cursor[NN];
__device__ int g_bsum[NB];
__device__ int g_boff[NB];
__device__ int g_sync;           // ticket for fused scan; reset by last block
__device__ int g_csr[NE];

// ---------------------------------------------------------------------------
// K1: in-degree counts, 4 edges/thread (g_cnt pre-zeroed by prior agg run)
// ---------------------------------------------------------------------------
__global__ void count_kernel(const int* __restrict__ ei) {
    int t = blockIdx.x * blockDim.x + threadIdx.x;
    if (t < NE / 4) {
        int4 d = ((const int4*)(ei + NE))[t];
        atomicAdd(&g_cnt[d.x], 1);
        atomicAdd(&g_cnt[d.y], 1);
        atomicAdd(&g_cnt[d.z], 1);
        atomicAdd(&g_cnt[d.w], 1);
    }
}

// ---------------------------------------------------------------------------
// K2: fused two-level exclusive scan. Per-block 1024-wide scan; the LAST
// block to finish (ticket) scans the 49 block totals into g_boff.
// ---------------------------------------------------------------------------
__global__ void __launch_bounds__(1024) scanAB_kernel() {
    __shared__ int wsum[32];
    __shared__ int sticket;
    int tid = threadIdx.x, lane = tid & 31, wid = tid >> 5;
    int i = blockIdx.x * 1024 + tid;
    int v = (i < NN) ? g_cnt[i] : 0;
    int s = v;
    #pragma unroll
    for (int o = 1; o < 32; o <<= 1) {
        int t = __shfl_up_sync(0xffffffffu, s, o);
        if (lane >= o) s += t;
    }
    if (lane == 31) wsum[wid] = s;
    __syncthreads();
    if (wid == 0) {
        int ws = wsum[lane];
        #pragma unroll
        for (int o = 1; o < 32; o <<= 1) {
            int t = __shfl_up_sync(0xffffffffu, ws, o);
            if (lane >= o) ws += t;
        }
        wsum[lane] = ws;
    }
    __syncthreads();
    int excl = ((wid == 0) ? 0 : wsum[wid - 1]) + s - v;
    if (i < NN) { g_rowstart[i] = excl; g_cursor[i] = excl; }
    if (tid == 0) {
        g_bsum[blockIdx.x] = wsum[31];
        __threadfence();
        sticket = atomicAdd(&g_sync, 1);
    }
    __syncthreads();
    if (sticket == NB - 1) {
        // last block: all g_bsum visible (fence-before-atomic on writers)
        __threadfence();
        if (tid < 32) {
            volatile int* vb = g_bsum;
            int v0 = (tid < NB) ? vb[tid] : 0;
            int v1 = (tid + 32 < NB) ? vb[tid + 32] : 0;
            int s0 = v0;
            #pragma unroll
            for (int o = 1; o < 32; o <<= 1) {
                int t = __shfl_up_sync(0xffffffffu, s0, o);
                if (tid >= o) s0 += t;
            }
            int tot0 = __shfl_sync(0xffffffffu, s0, 31);
            int s1 = v1;
            #pragma unroll
            for (int o = 1; o < 32; o <<= 1) {
                int t = __shfl_up_sync(0xffffffffu, s1, o);
                if (tid >= o) s1 += t;
            }
            if (tid < NB) g_boff[tid] = s0 - v0;
            if (tid + 32 < NB) g_boff[tid + 32] = tot0 + s1 - v1;
            if (tid == 0) g_sync = 0;   // reset ticket for next replay
        }
    }
}

// ---------------------------------------------------------------------------
// K3: fill CSR, 4 edges/thread. Final slot = local cursor + block offset.
// ---------------------------------------------------------------------------
__global__ void fill_kernel(const int* __restrict__ ei) {
    int t = blockIdx.x * blockDim.x + threadIdx.x;
    if (t < NE / 4) {
        int4 s = ((const int4*)ei)[t];
        int4 d = ((const int4*)(ei + NE))[t];
        int p0 = atomicAdd(&g_cursor[d.x], 1);
        int p1 = atomicAdd(&g_cursor[d.y], 1);
        int p2 = atomicAdd(&g_cursor[d.z], 1);
        int p3 = atomicAdd(&g_cursor[d.w], 1);
        g_csr[p0 + g_boff[d.x >> 10]] = s.x;
        g_csr[p1 + g_boff[d.y >> 10]] = s.y;
        g_csr[p2 + g_boff[d.z >> 10]] = s.z;
        g_csr[p3 + g_boff[d.w >> 10]] = s.w;
    }
}

// ---------------------------------------------------------------------------
// K4: gather-mean. Warp per row, lanes 0..23 own one float4 each, x4 unroll.
// Also resets g_cnt for the next replay.
// ---------------------------------------------------------------------------
__global__ void agg_kernel(const float* __restrict__ x) {
    int warp = (blockIdx.x * blockDim.x + threadIdx.x) >> 5;
    int lane = threadIdx.x & 31;
    if (warp >= NN) return;
    int deg = g_cnt[warp];
    if (lane == 0) g_cnt[warp] = 0;          // reset for next replay
    if (lane >= 24) return;
    int rs = g_rowstart[warp] + g_boff[warp >> 10];
    float4 a0 = make_float4(0.f, 0.f, 0.f, 0.f);
    float4 a1 = make_float4(0.f, 0.f, 0.f, 0.f);
    int j = 0;
    for (; j + 4 <= deg; j += 4) {
        int s0 = g_csr[rs + j];
        int s1 = g_csr[rs + j + 1];
        int s2 = g_csr[rs + j + 2];
        int s3 = g_csr[rs + j + 3];
        float4 v0 = ((const float4*)(x + (long)s0 * DIN))[lane];
        float4 v1 = ((const float4*)(x + (long)s1 * DIN))[lane];
        float4 v2 = ((const float4*)(x + (long)s2 * DIN))[lane];
        float4 v3 = ((const float4*)(x + (long)s3 * DIN))[lane];
        a0.x += v0.x; a0.y += v0.y; a0.z += v0.z; a0.w += v0.w;
        a1.x += v1.x; a1.y += v1.y; a1.z += v1.z; a1.w += v1.w;
        a0.x += v2.x; a0.y += v2.y; a0.z += v2.z; a0.w += v2.w;
        a1.x += v3.x; a1.y += v3.y; a1.z += v3.z; a1.w += v3.w;
    }
    for (; j < deg; j++) {
        int s0 = g_csr[rs + j];
        float4 v0 = ((const float4*)(x + (long)s0 * DIN))[lane];
        a0.x += v0.x; a0.y += v0.y; a0.z += v0.z; a0.w += v0.w;
    }
    float inv = 1.0f / (float)max(deg, 1);
    a0.x = (a0.x + a1.x) * inv;
    a0.y = (a0.y + a1.y) * inv;
    a0.z = (a0.z + a1.z) * inv;
    a0.w = (a0.w + a1.w) * inv;
    ((float4*)(g_agg + (long)warp * DIN))[lane] = a0;
}

// ---------------------------------------------------------------------------
// K5: out = relu( agg @ Wl^T + bl + x @ Wr^T )  -- packed fp32x2 FFMA.
// 256-thread block owns a full 32-row x 128-col tile. Weights for all 128
// cols in SMEM (stride 100 floats: conflict-free quarter-warp LDS.128).
// Data tiles double-buffered via cp.async; persistent grid of 148 blocks.
// Thread = (ct, rg): 4 cols {ct,ct+32,ct+64,ct+96} x 4 rows {rg*4..+3}.
// ---------------------------------------------------------------------------
__device__ __forceinline__ unsigned long long ffma2_(unsigned long long a,
                                                     unsigned long long b,
                                                     unsigned long long c) {
    unsigned long long d;
    asm("fma.rn.f32x2 %0, %1, %2, %3;" : "=l"(d) : "l"(a), "l"(b), "l"(c));
    return d;
}

#define WPAD 100
#define SM_WL 0
#define SM_WR 12800
#define SM_DATA 25600              // 2 bufs x (sx 3072 + sa 3072)
#define SM_FLOATS (25600 + 2 * 6144)   // 37888 floats = 151552 B

__device__ __forceinline__ void prefetch_tile(int t, float* sxb, float* sab,
                                              const float* __restrict__ x,
                                              int tid) {
    #pragma unroll
    for (int ii = 0; ii < 3; ii++) {
        int i = tid + ii * 256;           // 768 float4 per array
        int r = i / 24, q = i - r * 24;
        int gr = t * 32 + r; if (gr >= NN) gr = NN - 1;
        unsigned dx = (unsigned)__cvta_generic_to_shared(sxb + r * DIN + q * 4);
        unsigned da = (unsigned)__cvta_generic_to_shared(sab + r * DIN + q * 4);
        const float* gx = x + (long)gr * DIN + q * 4;
        const float* ga = g_agg + (long)gr * DIN + q * 4;
        asm volatile("cp.async.cg.shared.global [%0], [%1], 16;" :: "r"(dx), "l"(gx));
        asm volatile("cp.async.cg.shared.global [%0], [%1], 16;" :: "r"(da), "l"(ga));
    }
}

__global__ void __launch_bounds__(256, 1) gemm_kernel(
    const float* __restrict__ x, const float* __restrict__ Wl,
    const float* __restrict__ bl, const float* __restrict__ Wr,
    float* __restrict__ out) {
    extern __shared__ __align__(16) float sm[];
    float* sWl = sm + SM_WL;
    float* sWr = sm + SM_WR;
    int tid = threadIdx.x;

    // stage both weight matrices, col-major-ish padded rows of 100 floats
    for (int i = tid; i < DOUT * 24; i += 256) {
        int n = i / 24, q = i - n * 24;
        *(float4*)(sWl + n * WPAD + q * 4) = *(const float4*)(Wl + n * DIN + q * 4);
        *(float4*)(sWr + n * WPAD + q * 4) = *(const float4*)(Wr + n * DIN + q * 4);
    }

    int ct = tid & 31, rg = tid >> 5;
    float bj[4];
    #pragma unroll
    for (int j = 0; j < 4; j++) bj[j] = __ldg(bl + ct + 32 * j);

    int t0 = blockIdx.x;
    prefetch_tile(t0, sm + SM_DATA, sm + SM_DATA + 3072, x, tid);
    asm volatile("cp.async.commit_group;" ::: "memory");

    int p = 0;
    for (int t = t0; t < NT; t += gridDim.x) {
        __syncthreads();   // everyone done with buf 1-p (and weights on iter 0)
        int tn = t + gridDim.x;
        if (tn < NT)
            prefetch_tile(tn, sm + SM_DATA + (1 - p) * 6144,
                          sm + SM_DATA + (1 - p) * 6144 + 3072, x, tid);
        asm volatile("cp.async.commit_group;" ::: "memory");
        asm volatile("cp.async.wait_group 1;" ::: "memory");
        __syncthreads();   // buf p fully resident for all threads

        const float* sx = sm + SM_DATA + p * 6144;
        const float* sa = sx + 3072;

        unsigned long long acc[16];
        #pragma unroll
        for (int i = 0; i < 16; i++) acc[i] = 0ull;

        #pragma unroll 4
        for (int k = 0; k < DIN; k += 4) {
            ulonglong2 wl[4], wr[4];
            #pragma unroll
            for (int j = 0; j < 4; j++) {
                wl[j] = *(const ulonglong2*)(sWl + (ct + 32 * j) * WPAD + k);
                wr[j] = *(const ulonglong2*)(sWr + (ct + 32 * j) * WPAD + k);
            }
            #pragma unroll
            for (int r = 0; r < 4; r++) {
                int row = rg * 4 + r;
                ulonglong2 av = *(const ulonglong2*)(sa + row * DIN + k);
                ulonglong2 xv = *(const ulonglong2*)(sx + row * DIN + k);
                #pragma unroll
                for (int j = 0; j < 4; j++) {
                    unsigned long long a = acc[j * 4 + r];
                    a = ffma2_(wl[j].x, av.x, a);
                    a = ffma2_(wl[j].y, av.y, a);
                    a = ffma2_(wr[j].x, xv.x, a);
                    a = ffma2_(wr[j].y, xv.y, a);
                    acc[j * 4 + r] = a;
                }
            }
        }

        #pragma unroll
        for (int r = 0; r < 4; r++) {
            int row = t * 32 + rg * 4 + r;
            if (row < NN) {
                #pragma unroll
                for (int j = 0; j < 4; j++) {
                    unsigned long long a = acc[j * 4 + r];
                    float v = __uint_as_float((unsigned)(a & 0xffffffffull)) +
                              __uint_as_float((unsigned)(a >> 32)) + bj[j];
                    out[(long)row * DOUT + ct + 32 * j] = fmaxf(v, 0.f);
                }
            }
        }
        p ^= 1;
    }
}

// ---------------------------------------------------------------------------
extern "C" void kernel_launch(void* const* d_in, const int* in_sizes, int n_in,
                              void* d_out, int out_size) {
    const float* x  = (const float*)d_in[0];
    const int*   ei = (const int*)d_in[1];
    const float* Wl = (const float*)d_in[2];
    const float* bl = (const float*)d_in[3];
    const float* Wr = (const float*)d_in[4];
    float* out = (float*)d_out;

    cudaFuncSetAttribute(gemm_kernel, cudaFuncAttributeMaxDynamicSharedMemorySize,
                         SM_FLOATS * (int)sizeof(float));

    count_kernel<<<(NE / 4 + 255) / 256, 256>>>(ei);
    scanAB_kernel<<<NB, 1024>>>();
    fill_kernel<<<(NE / 4 + 255) / 256, 256>>>(ei);
    agg_kernel<<<(NN * 32 + 255) / 256, 256>>>(x);
    gemm_kernel<<<148, 256, SM_FLOATS * sizeof(float)>>>(x, Wl, bl, Wr, out);
}